// round 11
// baseline (speedup 1.0000x reference)
#include <cuda_runtime.h>

#define NN 100000
#define NE 1600000
#define NG 512
#define NPAD 128   // row padding: GEMM tail blocks read (zeroed) pad rows safely

// ---------------------------------------------------------------------------
// Scratch (device globals; allocation is forbidden)
// g_hf1: [NN+pad][128] f32 = [x1(32) | agg0(32) | agg1(32) | agg2(32)]
// g_hf2: [NN+pad][256] f32 = [x2(64) | agg0(64) | agg1(64) | agg2(64)]
// g_wp1/g_wp2: packed tf32 B operand, layout [nt][kt][g][tig][2]
// ---------------------------------------------------------------------------
__device__ __align__(16) float g_hf1[(size_t)(NN + NPAD) * 128];
__device__ __align__(16) float g_hf2[(size_t)(NN + NPAD) * 256];
__device__ __align__(16) float g_wp1[64 * 128];
__device__ __align__(16) float g_wp2[64 * 256];
__device__ int   g_deg[NN];
__device__ int   g_off[NN];
__device__ int   g_part[128];
__device__ int   g_cursor[NN];
__device__ int   g_eidx[NE];                      // src | (rel<<17)
__device__ float g_pool[NG * 64];

static __device__ __forceinline__ void red_add_v2(float* p, float2 v) {
    asm volatile("red.global.add.v2.f32 [%0], {%1,%2};"
                 :: "l"(p), "f"(v.x), "f"(v.y) : "memory");
}
static __device__ __forceinline__ float tf32r(float v) {
    unsigned u;
    asm("cvt.rna.tf32.f32 %0, %1;" : "=r"(u) : "f"(v));
    return __uint_as_float(u);
}
static __device__ __forceinline__ float4 f4tf32(float4 v) {
    v.x = tf32r(v.x); v.y = tf32r(v.y); v.z = tf32r(v.z); v.w = tf32r(v.w);
    return v;
}
static __device__ __forceinline__ void mma_tf32(float* d, unsigned a0, unsigned a1,
                                                unsigned a2, unsigned a3,
                                                unsigned b0, unsigned b1) {
    asm volatile("mma.sync.aligned.m16n8k8.row.col.f32.tf32.tf32.f32 "
                 "{%0,%1,%2,%3}, {%4,%5,%6,%7}, {%8,%9}, {%0,%1,%2,%3};"
                 : "+f"(d[0]), "+f"(d[1]), "+f"(d[2]), "+f"(d[3])
                 : "r"(a0), "r"(a1), "r"(a2), "r"(a3), "r"(b0), "r"(b1));
}

// ---------------------------------------------------------------------------
// init: zero deg/pool + embedding + pre-MLP -> g_hf1 cols 0..31
// ---------------------------------------------------------------------------
__global__ void init_embed_kernel(const int* __restrict__ nf,
                                  const float* __restrict__ se,
                                  const float* __restrict__ ce,
                                  const float* __restrict__ pw,
                                  const float* __restrict__ pb) {
    int idx = blockIdx.x * blockDim.x + threadIdx.x;
    int stride = gridDim.x * blockDim.x;
    for (int i = idx; i < NN; i += stride) g_deg[i] = 0;
    for (int i = idx; i < NG * 64; i += stride) g_pool[i] = 0.f;
    if (idx < NN * 32) {
        int i = idx >> 5, c = idx & 31;
        int s = nf[2 * i], col = nf[2 * i + 1];
        float acc = pb[c];
#pragma unroll
        for (int k = 0; k < 8; k++) acc = fmaf(se[s * 8 + k], pw[k * 32 + c], acc);
#pragma unroll
        for (int k = 0; k < 8; k++) acc = fmaf(ce[col * 8 + k], pw[(8 + k) * 32 + c], acc);
        g_hf1[(size_t)i * 128 + c] = fmaxf(acc, 0.f);
    }
}

// ---------------------------------------------------------------------------
// Weight prep: pack stacked [root; rel] into mma B-fragment order, tf32-rounded.
// ---------------------------------------------------------------------------
static __device__ __forceinline__ void pack_one(float* dst, int p, int KT, int C,
                                                const float* root, const float* rel) {
    int nt = p / (KT * 64);
    int kt = (p / 64) % KT;
    int q = p & 63;
    int g = q >> 3, tig = (q & 7) >> 1, h = q & 1;
    int n = nt * 8 + g;
    int k = kt * 8 + tig + 4 * h;
    float v = (k < C) ? root[k * 64 + n] : rel[(k - C) * 64 + n];
    dst[p] = tf32r(v);
}

__global__ void prep_w_kernel(const float* __restrict__ root1, const float* __restrict__ rel1,
                              const float* __restrict__ root2, const float* __restrict__ rel2) {
    int idx = blockIdx.x * blockDim.x + threadIdx.x;
    if (idx < 64 * 128) {
        pack_one(g_wp1, idx, 16, 32, root1, rel1);
    } else if (idx < 64 * 128 + 64 * 256) {
        pack_one(g_wp2, idx - 64 * 128, 32, 64, root2, rel2);
    }
}

// ---------------------------------------------------------------------------
// CSR build
// ---------------------------------------------------------------------------
__global__ void hist_kernel(const int* __restrict__ ei) {
    int e = blockIdx.x * blockDim.x + threadIdx.x;
    if (e < NE) atomicAdd(&g_deg[ei[NE + e]], 1);
}

// shfl-based block scan (1024 threads, 3 syncs)
__global__ void scan_a_kernel() {
    __shared__ int wsum[32];
    int tid = threadIdx.x;
    int wid = tid >> 5, lane = tid & 31;
    int i = blockIdx.x * 1024 + tid;
    int v = (i < NN) ? g_deg[i] : 0;
    int s = v;
#pragma unroll
    for (int ofs = 1; ofs < 32; ofs <<= 1) {
        int t = __shfl_up_sync(0xffffffffu, s, ofs);
        if (lane >= ofs) s += t;
    }
    if (lane == 31) wsum[wid] = s;
    __syncthreads();
    if (wid == 0) {
        int ws = wsum[lane];
#pragma unroll
        for (int ofs = 1; ofs < 32; ofs <<= 1) {
            int t = __shfl_up_sync(0xffffffffu, ws, ofs);
            if (lane >= ofs) ws += t;
        }
        wsum[lane] = ws;
    }
    __syncthreads();
    int base = (wid > 0) ? wsum[wid - 1] : 0;
    if (i < NN) g_off[i] = base + s - v;
    if (tid == 1023) g_part[blockIdx.x] = base + s;
}

__global__ void scan_b_kernel() {
    __shared__ int ws[4];
    __shared__ int s_prefix;
    int tid = threadIdx.x;
    int b = blockIdx.x;
    if (tid < 128) {
        int v = (tid < b) ? g_part[tid] : 0;
#pragma unroll
        for (int ofs = 16; ofs > 0; ofs >>= 1)
            v += __shfl_down_sync(0xffffffffu, v, ofs);
        if ((tid & 31) == 0) ws[tid >> 5] = v;
    }
    __syncthreads();
    if (tid == 0) s_prefix = ws[0] + ws[1] + ws[2] + ws[3];
    __syncthreads();
    int prefix = s_prefix;
    int i = b * 1024 + tid;
    if (i < NN) {
        int o = g_off[i] + prefix;
        g_off[i] = o;
        g_cursor[i] = o;
    }
}

__global__ void fill_kernel(const int* __restrict__ ei,
                            const int* __restrict__ et) {
    int e = blockIdx.x * blockDim.x + threadIdx.x;
    if (e >= NE) return;
    int dst = ei[NE + e];
    int pos = atomicAdd(&g_cursor[dst], 1);
    g_eidx[pos] = ei[e] | (et[e] << 17);
}

// ---------------------------------------------------------------------------
// gather1: ONE node per warp, lane = col (32 x 4B = 128B/edge), 4-edge pipeline.
// ---------------------------------------------------------------------------
__global__ __launch_bounds__(256) void gather1_kernel() {
    int node = blockIdx.x * 8 + (threadIdx.x >> 5);
    if (node >= NN) return;
    int lane = threadIdx.x & 31;
    const int* ep = g_eidx + g_off[node];
    int d = g_deg[node];

    float a0 = 0.f, a1 = 0.f, a2 = 0.f;
    int c0 = 0, c1 = 0, c2 = 0;

    int p0, p1, p2, p3;
    if (d >= 4) { p0 = ep[0]; p1 = ep[1]; p2 = ep[2]; p3 = ep[3]; }
    int i = 0;
    for (; i + 4 <= d; i += 4) {
        float v0 = __ldg(&g_hf1[(size_t)(p0 & 131071) * 128 + lane]);
        float v1 = __ldg(&g_hf1[(size_t)(p1 & 131071) * 128 + lane]);
        float v2 = __ldg(&g_hf1[(size_t)(p2 & 131071) * 128 + lane]);
        float v3 = __ldg(&g_hf1[(size_t)(p3 & 131071) * 128 + lane]);
        int r0 = p0 >> 17, r1 = p1 >> 17, r2 = p2 >> 17, r3 = p3 >> 17;
        int n0 = 0, n1 = 0, n2 = 0, n3 = 0;
        if (i + 8 <= d) { n0 = ep[i + 4]; n1 = ep[i + 5]; n2 = ep[i + 6]; n3 = ep[i + 7]; }
        if (r0 == 0) { a0 += v0; c0++; } else if (r0 == 1) { a1 += v0; c1++; } else { a2 += v0; c2++; }
        if (r1 == 0) { a0 += v1; c0++; } else if (r1 == 1) { a1 += v1; c1++; } else { a2 += v1; c2++; }
        if (r2 == 0) { a0 += v2; c0++; } else if (r2 == 1) { a1 += v2; c1++; } else { a2 += v2; c2++; }
        if (r3 == 0) { a0 += v3; c0++; } else if (r3 == 1) { a1 += v3; c1++; } else { a2 += v3; c2++; }
        p0 = n0; p1 = n1; p2 = n2; p3 = n3;
    }
    for (; i < d; i++) {
        int p = ep[i];
        float v = __ldg(&g_hf1[(size_t)(p & 131071) * 128 + lane]);
        int r = p >> 17;
        if (r == 0) { a0 += v; c0++; } else if (r == 1) { a1 += v; c1++; } else { a2 += v; c2++; }
    }
    float* o = g_hf1 + (size_t)node * 128 + 32 + lane;
    o[0]  = a0 * (1.f / max(c0, 1));
    o[32] = a1 * (1.f / max(c1, 1));
    o[64] = a2 * (1.f / max(c2, 1));
}

// ---------------------------------------------------------------------------
// gather2: ONE node per warp, lane = float2 (32 x 8B = 256B/edge), 4-edge pipeline.
// ---------------------------------------------------------------------------
__global__ __launch_bounds__(256) void gather2_kernel() {
    int node = blockIdx.x * 8 + (threadIdx.x >> 5);
    if (node >= NN) return;
    int lane = threadIdx.x & 31;
    const int* ep = g_eidx + g_off[node];
    int d = g_deg[node];

    float2 a0 = {0.f, 0.f}, a1 = a0, a2 = a0;
    int c0 = 0, c1 = 0, c2 = 0;

    int p0, p1, p2, p3;
    if (d >= 4) { p0 = ep[0]; p1 = ep[1]; p2 = ep[2]; p3 = ep[3]; }
    int i = 0;
    for (; i + 4 <= d; i += 4) {
        float2 v0 = __ldg((const float2*)(g_hf2 + (size_t)(p0 & 131071) * 256) + lane);
        float2 v1 = __ldg((const float2*)(g_hf2 + (size_t)(p1 & 131071) * 256) + lane);
        float2 v2 = __ldg((const float2*)(g_hf2 + (size_t)(p2 & 131071) * 256) + lane);
        float2 v3 = __ldg((const float2*)(g_hf2 + (size_t)(p3 & 131071) * 256) + lane);
        int r0 = p0 >> 17, r1 = p1 >> 17, r2 = p2 >> 17, r3 = p3 >> 17;
        int n0 = 0, n1 = 0, n2 = 0, n3 = 0;
        if (i + 8 <= d) { n0 = ep[i + 4]; n1 = ep[i + 5]; n2 = ep[i + 6]; n3 = ep[i + 7]; }
        if (r0 == 0) { a0.x += v0.x; a0.y += v0.y; c0++; }
        else if (r0 == 1) { a1.x += v0.x; a1.y += v0.y; c1++; }
        else { a2.x += v0.x; a2.y += v0.y; c2++; }
        if (r1 == 0) { a0.x += v1.x; a0.y += v1.y; c0++; }
        else if (r1 == 1) { a1.x += v1.x; a1.y += v1.y; c1++; }
        else { a2.x += v1.x; a2.y += v1.y; c2++; }
        if (r2 == 0) { a0.x += v2.x; a0.y += v2.y; c0++; }
        else if (r2 == 1) { a1.x += v2.x; a1.y += v2.y; c1++; }
        else { a2.x += v2.x; a2.y += v2.y; c2++; }
        if (r3 == 0) { a0.x += v3.x; a0.y += v3.y; c0++; }
        else if (r3 == 1) { a1.x += v3.x; a1.y += v3.y; c1++; }
        else { a2.x += v3.x; a2.y += v3.y; c2++; }
        p0 = n0; p1 = n1; p2 = n2; p3 = n3;
    }
    for (; i < d; i++) {
        int p = ep[i];
        float2 v = __ldg((const float2*)(g_hf2 + (size_t)(p & 131071) * 256) + lane);
        int r = p >> 17;
        if (r == 0) { a0.x += v.x; a0.y += v.y; c0++; }
        else if (r == 1) { a1.x += v.x; a1.y += v.y; c1++; }
        else { a2.x += v.x; a2.y += v.y; c2++; }
    }
    float s0 = 1.f / max(c0, 1), s1 = 1.f / max(c1, 1), s2 = 1.f / max(c2, 1);
    float* base = g_hf2 + (size_t)node * 256;
    *(float2*)(base + 64 + 2 * lane)  = make_float2(a0.x * s0, a0.y * s0);
    *(float2*)(base + 128 + 2 * lane) = make_float2(a1.x * s1, a1.y * s1);
    *(float2*)(base + 192 + 2 * lane) = make_float2(a2.x * s2, a2.y * s2);
}

// ---------------------------------------------------------------------------
// Hand-rolled tf32 mma GEMM (unchanged from R10 — validated at 270us/2.56e-4).
// ---------------------------------------------------------------------------
template <int LAYER>
__global__ __launch_bounds__(256) void gemm_mma_kernel(const float* __restrict__ bias,
                                                       const int* __restrict__ batch) {
    constexpr int KK = (LAYER == 1) ? 128 : 256;
    constexpr int KT = KK / 8;
    const float* H  = (LAYER == 1) ? g_hf1 : g_hf2;
    const float* WP = (LAYER == 1) ? g_wp1 : g_wp2;

    extern __shared__ __align__(16) char dsm[];
    float* s_a = (float*)dsm;                            // [128][68]
    float* s_b = (float*)(dsm + 128 * 68 * 4);           // [64*KK] packed

    int tid = threadIdx.x;
    int wid = tid >> 5, lane = tid & 31;
    int g = lane >> 2, tig = lane & 3;
    int n0 = blockIdx.x * 128;

    for (int q = tid; q < 64 * KK / 4; q += 256)
        ((float4*)s_b)[q] = ((const float4*)WP)[q];

    float d[8][4];
#pragma unroll
    for (int nt = 0; nt < 8; nt++)
#pragma unroll
        for (int c = 0; c < 4; c++) d[nt][c] = 0.f;

    const unsigned* ua = (const unsigned*)s_a;
    int arow0 = (wid * 16 + g) * 68;
    int arow1 = arow0 + 8 * 68;

#pragma unroll
    for (int kc = 0; kc < KK; kc += 64) {
        __syncthreads();
#pragma unroll
        for (int it = 0; it < 8; it++) {
            int q = tid + it * 256;
            int row = q >> 4, c4 = (q & 15) * 4;
            float4 v = *(const float4*)(H + (size_t)(n0 + row) * KK + kc + c4);
            *(float4*)(s_a + row * 68 + c4) = f4tf32(v);
        }
        __syncthreads();

        int kt0 = kc >> 3;
#pragma unroll
        for (int k8 = 0; k8 < 8; k8++) {
            int kb = k8 * 8 + tig;
            unsigned a0 = ua[arow0 + kb];
            unsigned a1 = ua[arow1 + kb];
            unsigned a2 = ua[arow0 + kb + 4];
            unsigned a3 = ua[arow1 + kb + 4];
            int bbase = ((kt0 + k8) * 32 + g * 4 + tig) * 2;
#pragma unroll
            for (int nt = 0; nt < 8; nt++) {
                uint2 b = *(const uint2*)(s_b + nt * (KT * 64) + bbase);
                mma_tf32(d[nt], a0, a1, a2, a3, b.x, b.y);
            }
        }
    }

    int r0 = n0 + wid * 16 + g;
    int r1 = r0 + 8;
#pragma unroll
    for (int nt = 0; nt < 8; nt++) {
        int c = nt * 8 + tig * 2;
        float2 bb = *(const float2*)(bias + c);
        float2 v0 = make_float2(fmaxf(d[nt][0] + bb.x, 0.f), fmaxf(d[nt][1] + bb.y, 0.f));
        float2 v1 = make_float2(fmaxf(d[nt][2] + bb.x, 0.f), fmaxf(d[nt][3] + bb.y, 0.f));
        if (LAYER == 1) {
            if (r0 < NN) *(float2*)(g_hf2 + (size_t)r0 * 256 + c) = v0;
            if (r1 < NN) *(float2*)(g_hf2 + (size_t)r1 * 256 + c) = v1;
        } else {
            if (r0 < NN) red_add_v2(&g_pool[batch[r0] * 64 + c], v0);
            if (r1 < NN) red_add_v2(&g_pool[batch[r1] * 64 + c], v1);
        }
    }
}

// ---------------------------------------------------------------------------
// Classifier (graph counts via binary search on sorted batch)
// ---------------------------------------------------------------------------
static __device__ __forceinline__ int lower_bound(const int* b, int v) {
    int lo = 0, hi = NN;
    while (lo < hi) { int m = (lo + hi) >> 1; if (b[m] < v) lo = m + 1; else hi = m; }
    return lo;
}

__global__ void cls_kernel(const int* __restrict__ batch,
                           const float* __restrict__ cw,
                           const float* __restrict__ cb,
                           float* __restrict__ out) {
    int idx = blockIdx.x * blockDim.x + threadIdx.x;
    if (idx >= NG * 10) return;
    int g = idx / 10, c = idx - g * 10;
    int cnt = lower_bound(batch, g + 1) - lower_bound(batch, g);
    float inv = 1.f / max(cnt, 1);
    float acc = 0.f;
#pragma unroll
    for (int k = 0; k < 64; k++) acc = fmaf(g_pool[g * 64 + k], cw[k * 10 + c], acc);
    out[idx] = acc * inv + cb[c];
}

// ---------------------------------------------------------------------------
extern "C" void kernel_launch(void* const* d_in, const int* in_sizes, int n_in,
                              void* d_out, int out_size) {
    const int*   nf    = (const int*)d_in[0];
    const int*   ei    = (const int*)d_in[1];
    const int*   et    = (const int*)d_in[2];
    const int*   batch = (const int*)d_in[3];
    const float* se    = (const float*)d_in[4];
    const float* ce    = (const float*)d_in[5];
    const float* pw    = (const float*)d_in[6];
    const float* pb    = (const float*)d_in[7];
    const float* root1 = (const float*)d_in[8];
    const float* rel1  = (const float*)d_in[9];
    const float* bias1 = (const float*)d_in[10];
    const float* root2 = (const float*)d_in[11];
    const float* rel2  = (const float*)d_in[12];
    const float* bias2 = (const float*)d_in[13];
    const float* cw    = (const float*)d_in[14];
    const float* cb    = (const float*)d_in[15];
    float* out = (float*)d_out;

    const int SMEM1 = 128 * 68 * 4 + 64 * 128 * 4;   // 67584
    const int SMEM2 = 128 * 68 * 4 + 64 * 256 * 4;   // 100352
    cudaFuncSetAttribute(gemm_mma_kernel<1>, cudaFuncAttributeMaxDynamicSharedMemorySize, SMEM1);
    cudaFuncSetAttribute(gemm_mma_kernel<2>, cudaFuncAttributeMaxDynamicSharedMemorySize, SMEM2);

    init_embed_kernel<<<12500, 256>>>(nf, se, ce, pw, pb);
    prep_w_kernel<<<96, 256>>>(root1, rel1, root2, rel2);
    hist_kernel<<<(NE + 255) / 256, 256>>>(ei);
    scan_a_kernel<<<98, 1024>>>();
    scan_b_kernel<<<98, 1024>>>();
    fill_kernel<<<(NE + 255) / 256, 256>>>(ei, et);

    gather1_kernel<<<(NN + 7) / 8, 256>>>();
    gemm_mma_kernel<1><<<(NN + 127) / 128, 256, SMEM1>>>(bias1, batch);

    gather2_kernel<<<(NN + 7) / 8, 256>>>();
    gemm_mma_kernel<2><<<(NN + 127) / 128, 256, SMEM2>>>(bias2, batch);

    cls_kernel<<<20, 256>>>(batch, cw, cb, out);
}

// round 12
// speedup vs baseline: 1.0317x; 1.0317x over previous
#include <cuda_runtime.h>

#define NN 100000
#define NE 1600000
#define NG 512
#define NPAD 128   // row padding: GEMM tail blocks read (zeroed) pad rows safely

// ---------------------------------------------------------------------------
// Scratch (device globals; allocation is forbidden)
// g_hf1: [NN+pad][128] f32 = [x1(32) | agg0(32) | agg1(32) | agg2(32)]
// g_hf2: [NN+pad][256] f32 = [x2(64) | agg0(64) | agg1(64) | agg2(64)]
// g_wp1/g_wp2: packed tf32 B operand, layout [nt][kt][g][tig][2]
// ---------------------------------------------------------------------------
__device__ __align__(16) float g_hf1[(size_t)(NN + NPAD) * 128];
__device__ __align__(16) float g_hf2[(size_t)(NN + NPAD) * 256];
__device__ __align__(16) float g_wp1[64 * 128];
__device__ __align__(16) float g_wp2[64 * 256];
__device__ int   g_deg[NN];
__device__ int   g_off[NN];
__device__ int   g_part[128];
__device__ int   g_cursor[NN];
__device__ int   g_eidx[NE];                      // src | (rel<<17)
__device__ float g_pool[NG * 64];

static __device__ __forceinline__ void red_add_v2(float* p, float2 v) {
    asm volatile("red.global.add.v2.f32 [%0], {%1,%2};"
                 :: "l"(p), "f"(v.x), "f"(v.y) : "memory");
}
static __device__ __forceinline__ void f4add(float4& a, float4 b) {
    a.x += b.x; a.y += b.y; a.z += b.z; a.w += b.w;
}
static __device__ __forceinline__ float4 f4scale(float4 a, float s) {
    return make_float4(a.x * s, a.y * s, a.z * s, a.w * s);
}
static __device__ __forceinline__ float tf32r(float v) {
    unsigned u;
    asm("cvt.rna.tf32.f32 %0, %1;" : "=r"(u) : "f"(v));
    return __uint_as_float(u);
}
static __device__ __forceinline__ float4 f4tf32(float4 v) {
    v.x = tf32r(v.x); v.y = tf32r(v.y); v.z = tf32r(v.z); v.w = tf32r(v.w);
    return v;
}
static __device__ __forceinline__ void mma_tf32(float* d, unsigned a0, unsigned a1,
                                                unsigned a2, unsigned a3,
                                                unsigned b0, unsigned b1) {
    asm volatile("mma.sync.aligned.m16n8k8.row.col.f32.tf32.tf32.f32 "
                 "{%0,%1,%2,%3}, {%4,%5,%6,%7}, {%8,%9}, {%0,%1,%2,%3};"
                 : "+f"(d[0]), "+f"(d[1]), "+f"(d[2]), "+f"(d[3])
                 : "r"(a0), "r"(a1), "r"(a2), "r"(a3), "r"(b0), "r"(b1));
}

// ---------------------------------------------------------------------------
// init: zero deg/pool + embedding + pre-MLP -> g_hf1 cols 0..31
// ---------------------------------------------------------------------------
__global__ void init_embed_kernel(const int* __restrict__ nf,
                                  const float* __restrict__ se,
                                  const float* __restrict__ ce,
                                  const float* __restrict__ pw,
                                  const float* __restrict__ pb) {
    int idx = blockIdx.x * blockDim.x + threadIdx.x;
    int stride = gridDim.x * blockDim.x;
    for (int i = idx; i < NN; i += stride) g_deg[i] = 0;
    for (int i = idx; i < NG * 64; i += stride) g_pool[i] = 0.f;
    if (idx < NN * 32) {
        int i = idx >> 5, c = idx & 31;
        int s = nf[2 * i], col = nf[2 * i + 1];
        float acc = pb[c];
#pragma unroll
        for (int k = 0; k < 8; k++) acc = fmaf(se[s * 8 + k], pw[k * 32 + c], acc);
#pragma unroll
        for (int k = 0; k < 8; k++) acc = fmaf(ce[col * 8 + k], pw[(8 + k) * 32 + c], acc);
        g_hf1[(size_t)i * 128 + c] = fmaxf(acc, 0.f);
    }
}

// ---------------------------------------------------------------------------
// Weight prep: pack stacked [root; rel] into mma B-fragment order, tf32-rounded.
// ---------------------------------------------------------------------------
static __device__ __forceinline__ void pack_one(float* dst, int p, int KT, int C,
                                                const float* root, const float* rel) {
    int nt = p / (KT * 64);
    int kt = (p / 64) % KT;
    int q = p & 63;
    int g = q >> 3, tig = (q & 7) >> 1, h = q & 1;
    int n = nt * 8 + g;
    int k = kt * 8 + tig + 4 * h;
    float v = (k < C) ? root[k * 64 + n] : rel[(k - C) * 64 + n];
    dst[p] = tf32r(v);
}

__global__ void prep_w_kernel(const float* __restrict__ root1, const float* __restrict__ rel1,
                              const float* __restrict__ root2, const float* __restrict__ rel2) {
    int idx = blockIdx.x * blockDim.x + threadIdx.x;
    if (idx < 64 * 128) {
        pack_one(g_wp1, idx, 16, 32, root1, rel1);
    } else if (idx < 64 * 128 + 64 * 256) {
        pack_one(g_wp2, idx - 64 * 128, 32, 64, root2, rel2);
    }
}

// ---------------------------------------------------------------------------
// CSR build (shfl scans, validated R11)
// ---------------------------------------------------------------------------
__global__ void hist_kernel(const int* __restrict__ ei) {
    int e = blockIdx.x * blockDim.x + threadIdx.x;
    if (e < NE) atomicAdd(&g_deg[ei[NE + e]], 1);
}

__global__ void scan_a_kernel() {
    __shared__ int wsum[32];
    int tid = threadIdx.x;
    int wid = tid >> 5, lane = tid & 31;
    int i = blockIdx.x * 1024 + tid;
    int v = (i < NN) ? g_deg[i] : 0;
    int s = v;
#pragma unroll
    for (int ofs = 1; ofs < 32; ofs <<= 1) {
        int t = __shfl_up_sync(0xffffffffu, s, ofs);
        if (lane >= ofs) s += t;
    }
    if (lane == 31) wsum[wid] = s;
    __syncthreads();
    if (wid == 0) {
        int ws = wsum[lane];
#pragma unroll
        for (int ofs = 1; ofs < 32; ofs <<= 1) {
            int t = __shfl_up_sync(0xffffffffu, ws, ofs);
            if (lane >= ofs) ws += t;
        }
        wsum[lane] = ws;
    }
    __syncthreads();
    int base = (wid > 0) ? wsum[wid - 1] : 0;
    if (i < NN) g_off[i] = base + s - v;
    if (tid == 1023) g_part[blockIdx.x] = base + s;
}

__global__ void scan_b_kernel() {
    __shared__ int ws[4];
    __shared__ int s_prefix;
    int tid = threadIdx.x;
    int b = blockIdx.x;
    if (tid < 128) {
        int v = (tid < b) ? g_part[tid] : 0;
#pragma unroll
        for (int ofs = 16; ofs > 0; ofs >>= 1)
            v += __shfl_down_sync(0xffffffffu, v, ofs);
        if ((tid & 31) == 0) ws[tid >> 5] = v;
    }
    __syncthreads();
    if (tid == 0) s_prefix = ws[0] + ws[1] + ws[2] + ws[3];
    __syncthreads();
    int prefix = s_prefix;
    int i = b * 1024 + tid;
    if (i < NN) {
        int o = g_off[i] + prefix;
        g_off[i] = o;
        g_cursor[i] = o;
    }
}

__global__ void fill_kernel(const int* __restrict__ ei,
                            const int* __restrict__ et) {
    int e = blockIdx.x * blockDim.x + threadIdx.x;
    if (e >= NE) return;
    int dst = ei[NE + e];
    int pos = atomicAdd(&g_cursor[dst], 1);
    g_eidx[pos] = ei[e] | (et[e] << 17);
}

// ---------------------------------------------------------------------------
// gather1: 4 nodes/warp (8 lanes x float4 over 32 cols), 4-edge pipeline.
// ---------------------------------------------------------------------------
__global__ __launch_bounds__(256) void gather1_kernel() {
    int warp = blockIdx.x * 8 + (threadIdx.x >> 5);
    int lane = threadIdx.x & 31;
    int sub = lane & 7;
    int node = warp * 4 + (lane >> 3);
    bool valid = node < NN;
    int off = valid ? g_off[node] : 0;
    int d   = valid ? g_deg[node] : 0;
    const int* ep = g_eidx + off;

    int dmax = d;
    dmax = max(dmax, __shfl_xor_sync(0xffffffffu, dmax, 8));
    dmax = max(dmax, __shfl_xor_sync(0xffffffffu, dmax, 16));

    float4 a0 = {0,0,0,0}, a1 = a0, a2 = a0;
    int c0 = 0, c1 = 0, c2 = 0;

    int p0 = 0, p1 = 0, p2 = 0, p3 = 0;
    if (0 < d) p0 = __ldg(ep);
    if (1 < d) p1 = __ldg(ep + 1);
    if (2 < d) p2 = __ldg(ep + 2);
    if (3 < d) p3 = __ldg(ep + 3);
    int i = 0;
    for (; i + 4 <= dmax; i += 4) {
        float4 v0 = {0,0,0,0}, v1 = v0, v2 = v0, v3 = v0;
        int r0 = (i < d)     ? (p0 >> 17) : 3;
        int r1 = (i + 1 < d) ? (p1 >> 17) : 3;
        int r2 = (i + 2 < d) ? (p2 >> 17) : 3;
        int r3 = (i + 3 < d) ? (p3 >> 17) : 3;
        if (i < d)     v0 = *(const float4*)(g_hf1 + (size_t)(p0 & 131071) * 128 + sub * 4);
        if (i + 1 < d) v1 = *(const float4*)(g_hf1 + (size_t)(p1 & 131071) * 128 + sub * 4);
        if (i + 2 < d) v2 = *(const float4*)(g_hf1 + (size_t)(p2 & 131071) * 128 + sub * 4);
        if (i + 3 < d) v3 = *(const float4*)(g_hf1 + (size_t)(p3 & 131071) * 128 + sub * 4);
        int q0 = 0, q1 = 0, q2 = 0, q3 = 0;
        if (i + 4 < d) q0 = __ldg(ep + i + 4);
        if (i + 5 < d) q1 = __ldg(ep + i + 5);
        if (i + 6 < d) q2 = __ldg(ep + i + 6);
        if (i + 7 < d) q3 = __ldg(ep + i + 7);
        if (r0 == 0) { f4add(a0, v0); c0++; } else if (r0 == 1) { f4add(a1, v0); c1++; } else if (r0 == 2) { f4add(a2, v0); c2++; }
        if (r1 == 0) { f4add(a0, v1); c0++; } else if (r1 == 1) { f4add(a1, v1); c1++; } else if (r1 == 2) { f4add(a2, v1); c2++; }
        if (r2 == 0) { f4add(a0, v2); c0++; } else if (r2 == 1) { f4add(a1, v2); c1++; } else if (r2 == 2) { f4add(a2, v2); c2++; }
        if (r3 == 0) { f4add(a0, v3); c0++; } else if (r3 == 1) { f4add(a1, v3); c1++; } else if (r3 == 2) { f4add(a2, v3); c2++; }
        p0 = q0; p1 = q1; p2 = q2; p3 = q3;
    }
    for (; i < dmax; i++) {
        if (i < d) {
            int p = __ldg(ep + i);
            int r = p >> 17;
            float4 v = *(const float4*)(g_hf1 + (size_t)(p & 131071) * 128 + sub * 4);
            if (r == 0) { f4add(a0, v); c0++; } else if (r == 1) { f4add(a1, v); c1++; } else { f4add(a2, v); c2++; }
        }
    }
    if (valid) {
        float* o = g_hf1 + (size_t)node * 128 + 32 + sub * 4;
        *(float4*)(o)      = f4scale(a0, 1.f / max(c0, 1));
        *(float4*)(o + 32) = f4scale(a1, 1.f / max(c1, 1));
        *(float4*)(o + 64) = f4scale(a2, 1.f / max(c2, 1));
    }
}

// ---------------------------------------------------------------------------
// gather2: 2 nodes/warp (16 lanes x float4 over 64 cols), 4-edge pipeline.
// ---------------------------------------------------------------------------
__global__ __launch_bounds__(256) void gather2_kernel() {
    int warp = blockIdx.x * 8 + (threadIdx.x >> 5);
    int lane = threadIdx.x & 31;
    int sub = lane & 15;
    int node = warp * 2 + (lane >> 4);
    bool valid = node < NN;
    int off = valid ? g_off[node] : 0;
    int d   = valid ? g_deg[node] : 0;
    const int* ep = g_eidx + off;

    int dmax = max(d, __shfl_xor_sync(0xffffffffu, d, 16));

    float4 a0 = {0,0,0,0}, a1 = a0, a2 = a0;
    int c0 = 0, c1 = 0, c2 = 0;

    int p0 = 0, p1 = 0, p2 = 0, p3 = 0;
    if (0 < d) p0 = __ldg(ep);
    if (1 < d) p1 = __ldg(ep + 1);
    if (2 < d) p2 = __ldg(ep + 2);
    if (3 < d) p3 = __ldg(ep + 3);
    int i = 0;
    for (; i + 4 <= dmax; i += 4) {
        float4 v0 = {0,0,0,0}, v1 = v0, v2 = v0, v3 = v0;
        int r0 = (i < d)     ? (p0 >> 17) : 3;
        int r1 = (i + 1 < d) ? (p1 >> 17) : 3;
        int r2 = (i + 2 < d) ? (p2 >> 17) : 3;
        int r3 = (i + 3 < d) ? (p3 >> 17) : 3;
        if (i < d)     v0 = *(const float4*)(g_hf2 + (size_t)(p0 & 131071) * 256 + sub * 4);
        if (i + 1 < d) v1 = *(const float4*)(g_hf2 + (size_t)(p1 & 131071) * 256 + sub * 4);
        if (i + 2 < d) v2 = *(const float4*)(g_hf2 + (size_t)(p2 & 131071) * 256 + sub * 4);
        if (i + 3 < d) v3 = *(const float4*)(g_hf2 + (size_t)(p3 & 131071) * 256 + sub * 4);
        int q0 = 0, q1 = 0, q2 = 0, q3 = 0;
        if (i + 4 < d) q0 = __ldg(ep + i + 4);
        if (i + 5 < d) q1 = __ldg(ep + i + 5);
        if (i + 6 < d) q2 = __ldg(ep + i + 6);
        if (i + 7 < d) q3 = __ldg(ep + i + 7);
        if (r0 == 0) { f4add(a0, v0); c0++; } else if (r0 == 1) { f4add(a1, v0); c1++; } else if (r0 == 2) { f4add(a2, v0); c2++; }
        if (r1 == 0) { f4add(a0, v1); c0++; } else if (r1 == 1) { f4add(a1, v1); c1++; } else if (r1 == 2) { f4add(a2, v1); c2++; }
        if (r2 == 0) { f4add(a0, v2); c0++; } else if (r2 == 1) { f4add(a1, v2); c1++; } else if (r2 == 2) { f4add(a2, v2); c2++; }
        if (r3 == 0) { f4add(a0, v3); c0++; } else if (r3 == 1) { f4add(a1, v3); c1++; } else if (r3 == 2) { f4add(a2, v3); c2++; }
        p0 = q0; p1 = q1; p2 = q2; p3 = q3;
    }
    for (; i < dmax; i++) {
        if (i < d) {
            int p = __ldg(ep + i);
            int r = p >> 17;
            float4 v = *(const float4*)(g_hf2 + (size_t)(p & 131071) * 256 + sub * 4);
            if (r == 0) { f4add(a0, v); c0++; } else if (r == 1) { f4add(a1, v); c1++; } else { f4add(a2, v); c2++; }
        }
    }
    if (valid) {
        float* o = g_hf2 + (size_t)node * 256 + 64 + sub * 4;
        *(float4*)(o)       = f4scale(a0, 1.f / max(c0, 1));
        *(float4*)(o + 64)  = f4scale(a1, 1.f / max(c1, 1));
        *(float4*)(o + 128) = f4scale(a2, 1.f / max(c2, 1));
    }
}

// ---------------------------------------------------------------------------
// Hand-rolled tf32 mma GEMM (unchanged — validated at 270us/2.56e-4).
// ---------------------------------------------------------------------------
template <int LAYER>
__global__ __launch_bounds__(256) void gemm_mma_kernel(const float* __restrict__ bias,
                                                       const int* __restrict__ batch) {
    constexpr int KK = (LAYER == 1) ? 128 : 256;
    constexpr int KT = KK / 8;
    const float* H  = (LAYER == 1) ? g_hf1 : g_hf2;
    const float* WP = (LAYER == 1) ? g_wp1 : g_wp2;

    extern __shared__ __align__(16) char dsm[];
    float* s_a = (float*)dsm;                            // [128][68]
    float* s_b = (float*)(dsm + 128 * 68 * 4);           // [64*KK] packed

    int tid = threadIdx.x;
    int wid = tid >> 5, lane = tid & 31;
    int g = lane >> 2, tig = lane & 3;
    int n0 = blockIdx.x * 128;

    for (int q = tid; q < 64 * KK / 4; q += 256)
        ((float4*)s_b)[q] = ((const float4*)WP)[q];

    float d[8][4];
#pragma unroll
    for (int nt = 0; nt < 8; nt++)
#pragma unroll
        for (int c = 0; c < 4; c++) d[nt][c] = 0.f;

    const unsigned* ua = (const unsigned*)s_a;
    int arow0 = (wid * 16 + g) * 68;
    int arow1 = arow0 + 8 * 68;

#pragma unroll
    for (int kc = 0; kc < KK; kc += 64) {
        __syncthreads();
#pragma unroll
        for (int it = 0; it < 8; it++) {
            int q = tid + it * 256;
            int row = q >> 4, c4 = (q & 15) * 4;
            float4 v = *(const float4*)(H + (size_t)(n0 + row) * KK + kc + c4);
            *(float4*)(s_a + row * 68 + c4) = f4tf32(v);
        }
        __syncthreads();

        int kt0 = kc >> 3;
#pragma unroll
        for (int k8 = 0; k8 < 8; k8++) {
            int kb = k8 * 8 + tig;
            unsigned a0 = ua[arow0 + kb];
            unsigned a1 = ua[arow1 + kb];
            unsigned a2 = ua[arow0 + kb + 4];
            unsigned a3 = ua[arow1 + kb + 4];
            int bbase = ((kt0 + k8) * 32 + g * 4 + tig) * 2;
#pragma unroll
            for (int nt = 0; nt < 8; nt++) {
                uint2 b = *(const uint2*)(s_b + nt * (KT * 64) + bbase);
                mma_tf32(d[nt], a0, a1, a2, a3, b.x, b.y);
            }
        }
    }

    int r0 = n0 + wid * 16 + g;
    int r1 = r0 + 8;
#pragma unroll
    for (int nt = 0; nt < 8; nt++) {
        int c = nt * 8 + tig * 2;
        float2 bb = *(const float2*)(bias + c);
        float2 v0 = make_float2(fmaxf(d[nt][0] + bb.x, 0.f), fmaxf(d[nt][1] + bb.y, 0.f));
        float2 v1 = make_float2(fmaxf(d[nt][2] + bb.x, 0.f), fmaxf(d[nt][3] + bb.y, 0.f));
        if (LAYER == 1) {
            if (r0 < NN) *(float2*)(g_hf2 + (size_t)r0 * 256 + c) = v0;
            if (r1 < NN) *(float2*)(g_hf2 + (size_t)r1 * 256 + c) = v1;
        } else {
            if (r0 < NN) red_add_v2(&g_pool[batch[r0] * 64 + c], v0);
            if (r1 < NN) red_add_v2(&g_pool[batch[r1] * 64 + c], v1);
        }
    }
}

// ---------------------------------------------------------------------------
// Classifier (graph counts via binary search on sorted batch)
// ---------------------------------------------------------------------------
static __device__ __forceinline__ int lower_bound(const int* b, int v) {
    int lo = 0, hi = NN;
    while (lo < hi) { int m = (lo + hi) >> 1; if (b[m] < v) lo = m + 1; else hi = m; }
    return lo;
}

__global__ void cls_kernel(const int* __restrict__ batch,
                           const float* __restrict__ cw,
                           const float* __restrict__ cb,
                           float* __restrict__ out) {
    int idx = blockIdx.x * blockDim.x + threadIdx.x;
    if (idx >= NG * 10) return;
    int g = idx / 10, c = idx - g * 10;
    int cnt = lower_bound(batch, g + 1) - lower_bound(batch, g);
    float inv = 1.f / max(cnt, 1);
    float acc = 0.f;
#pragma unroll
    for (int k = 0; k < 64; k++) acc = fmaf(g_pool[g * 64 + k], cw[k * 10 + c], acc);
    out[idx] = acc * inv + cb[c];
}

// ---------------------------------------------------------------------------
extern "C" void kernel_launch(void* const* d_in, const int* in_sizes, int n_in,
                              void* d_out, int out_size) {
    const int*   nf    = (const int*)d_in[0];
    const int*   ei    = (const int*)d_in[1];
    const int*   et    = (const int*)d_in[2];
    const int*   batch = (const int*)d_in[3];
    const float* se    = (const float*)d_in[4];
    const float* ce    = (const float*)d_in[5];
    const float* pw    = (const float*)d_in[6];
    const float* pb    = (const float*)d_in[7];
    const float* root1 = (const float*)d_in[8];
    const float* rel1  = (const float*)d_in[9];
    const float* bias1 = (const float*)d_in[10];
    const float* root2 = (const float*)d_in[11];
    const float* rel2  = (const float*)d_in[12];
    const float* bias2 = (const float*)d_in[13];
    const float* cw    = (const float*)d_in[14];
    const float* cb    = (const float*)d_in[15];
    float* out = (float*)d_out;

    const int SMEM1 = 128 * 68 * 4 + 64 * 128 * 4;   // 67584
    const int SMEM2 = 128 * 68 * 4 + 64 * 256 * 4;   // 100352
    cudaFuncSetAttribute(gemm_mma_kernel<1>, cudaFuncAttributeMaxDynamicSharedMemorySize, SMEM1);
    cudaFuncSetAttribute(gemm_mma_kernel<2>, cudaFuncAttributeMaxDynamicSharedMemorySize, SMEM2);

    init_embed_kernel<<<12500, 256>>>(nf, se, ce, pw, pb);
    prep_w_kernel<<<96, 256>>>(root1, rel1, root2, rel2);
    hist_kernel<<<(NE + 255) / 256, 256>>>(ei);
    scan_a_kernel<<<98, 1024>>>();
    scan_b_kernel<<<98, 1024>>>();
    fill_kernel<<<(NE + 255) / 256, 256>>>(ei, et);

    gather1_kernel<<<(NN + 31) / 32, 256>>>();
    gemm_mma_kernel<1><<<(NN + 127) / 128, 256, SMEM1>>>(bias1, batch);

    gather2_kernel<<<(NN + 15) / 16, 256>>>();
    gemm_mma_kernel<2><<<(NN + 127) / 128, 256, SMEM2>>>(bias2, batch);

    cls_kernel<<<20, 256>>>(batch, cw, cb, out);
}